// round 7
// baseline (speedup 1.0000x reference)
#include <cuda_runtime.h>

// Warper3d: 3D trilinear warp (grid_sample, align_corners=False, border pad).
//   img : [B=4, 1, D=64, H=192, W=192] f32
//   flow: [B=4, 3, D=64, H=192, W=192] f32
//   out : [B=4, 1, D=64, H=192, W=192] f32
//
// R3-R6 evidence: global-gather version is pinned at L1tex~80% (random
// per-lane rows => ~20 wavefronts per gather instr; irreducible via LDG).
// This version stages a (14z x 14y x 192x) img tile (+/-3 halo, border-
// clamped rows) in 147KB smem and gathers via LDS; out-of-halo voxels
// (~2-3%, |flow|>~2.5) take an exact global fallback. Flow/out stream
// coalesced. Expect DRAM-bound.

#define BB 4
#define DD 64
#define HH 192
#define WW 192
#define SP (DD * HH * WW)

#define YT 8
#define ZT 8
#define HALO 3
#define TILE_Y (YT + 2 * HALO)     // 14
#define TILE_Z (ZT + 2 * HALO)     // 14
#define PITCH  WW                  // 192 floats per tile row
#define TILE_FLOATS (TILE_Z * TILE_Y * PITCH)   // 37,632 -> 150,528 B
#define NTHREADS 384               // 192 x-lanes * 2 (y,z)-pairs

__global__ __launch_bounds__(NTHREADS)
void warp3d_kernel(const float* __restrict__ img,
                   const float* __restrict__ flow,
                   float* __restrict__ out)
{
    extern __shared__ float tile[];

    const int tid   = threadIdx.x;
    const int ybase = blockIdx.x * YT;
    const int zbase = blockIdx.y * ZT;
    const int b     = blockIdx.z;

    const float* ib = img + (size_t)b * SP;
    const float* fb = flow + (size_t)b * 3 * SP;
    float* ob = out + (size_t)b * SP;

    // ---- stage tile: rows (zbase-3..zbase+10) x (ybase-3..ybase+10), clamped
    {
        const int NROW = TILE_Z * TILE_Y;           // 196
        const int QPR  = WW / 4;                    // 48 float4 per row
        #pragma unroll 4
        for (int j = tid; j < NROW * QPR; j += NTHREADS) {
            int row = j / QPR;
            int q   = j - row * QPR;
            int ty  = row % TILE_Y;
            int tz  = row / TILE_Y;
            int gy  = min(max(ybase - HALO + ty, 0), HH - 1);
            int gz  = min(max(zbase - HALO + tz, 0), DD - 1);
            float4 v = __ldg((const float4*)(ib + (gz * HH + gy) * WW + 4 * q));
            *(float4*)(tile + row * PITCH + 4 * q) = v;
        }
    }
    __syncthreads();

    const int x    = tid % WW;                      // lane-contiguous x
    const int pair = tid / WW;                      // 0 or 1

    // Reference composition gx=2v/(S-1)-1; ix=((gx+1)*S-1)/2 == v*S/(S-1)-0.5
    const float KX = (float)WW / (float)(WW - 1);
    const float KY = (float)HH / (float)(HH - 1);
    const float KZ = (float)DD / (float)(DD - 1);

    #pragma unroll 4
    for (int c = pair; c < YT * ZT; c += 2) {
        int y = ybase + (c % YT);
        int z = zbase + (c / YT);
        int s = (z * HH + y) * WW + x;

        float fx = __ldcs(fb + s);
        float fy = __ldcs(fb + SP + s);
        float fz = __ldcs(fb + 2 * SP + s);

        float ix = fmaf((float)x + fx, KX, -0.5f);
        float iy = fmaf((float)y + fy, KY, -0.5f);
        float iz = fmaf((float)z + fz, KZ, -0.5f);
        ix = fminf(fmaxf(ix, 0.0f), (float)(WW - 1));
        iy = fminf(fmaxf(iy, 0.0f), (float)(HH - 1));
        iz = fminf(fmaxf(iz, 0.0f), (float)(DD - 1));

        float x0f = floorf(ix); float wx = ix - x0f;
        float y0f = floorf(iy); float wy = iy - y0f;
        float z0f = floorf(iz); float wz = iz - z0f;

        int x0 = (int)x0f; int x1 = min(x0 + 1, WW - 1);
        int y0 = (int)y0f; int y1 = min(y0 + 1, HH - 1);
        int z0 = (int)z0f; int z1 = min(z0 + 1, DD - 1);

        float v000, v001, v010, v011, v100, v101, v110, v111;

        int ty0 = y0 - (ybase - HALO);
        int ty1 = y1 - (ybase - HALO);
        int tz0 = z0 - (zbase - HALO);
        int tz1 = z1 - (zbase - HALO);

        bool in_tile = (ty0 >= 0) & (ty1 < TILE_Y) & (tz0 >= 0) & (tz1 < TILE_Z);

        if (in_tile) {
            const float* t00 = tile + (tz0 * TILE_Y + ty0) * PITCH;
            const float* t01 = tile + (tz0 * TILE_Y + ty1) * PITCH;
            const float* t10 = tile + (tz1 * TILE_Y + ty0) * PITCH;
            const float* t11 = tile + (tz1 * TILE_Y + ty1) * PITCH;
            v000 = t00[x0]; v001 = t00[x1];
            v010 = t01[x0]; v011 = t01[x1];
            v100 = t10[x0]; v101 = t10[x1];
            v110 = t11[x0]; v111 = t11[x1];
        } else {
            // rare (~2-3%): exact global gather
            const float* p00 = ib + (z0 * HH + y0) * WW;
            const float* p01 = ib + (z0 * HH + y1) * WW;
            const float* p10 = ib + (z1 * HH + y0) * WW;
            const float* p11 = ib + (z1 * HH + y1) * WW;
            v000 = __ldg(p00 + x0); v001 = __ldg(p00 + x1);
            v010 = __ldg(p01 + x0); v011 = __ldg(p01 + x1);
            v100 = __ldg(p10 + x0); v101 = __ldg(p10 + x1);
            v110 = __ldg(p11 + x0); v111 = __ldg(p11 + x1);
        }

        float c00 = fmaf(wx, v001 - v000, v000);
        float c01 = fmaf(wx, v011 - v010, v010);
        float c10 = fmaf(wx, v101 - v100, v100);
        float c11 = fmaf(wx, v111 - v110, v110);
        float c0  = fmaf(wy, c01 - c00, c00);
        float c1  = fmaf(wy, c11 - c10, c10);
        float r   = fmaf(wz, c1 - c0, c0);

        __stcs(ob + s, r);
    }
}

extern "C" void kernel_launch(void* const* d_in, const int* in_sizes, int n_in,
                              void* d_out, int out_size)
{
    const float* img  = (const float*)d_in[0];
    const float* flow = (const float*)d_in[1];
    float* out = (float*)d_out;

    static bool attr_set = false;
    // idempotent; safe to call every launch (not a stream op, capture-legal)
    cudaFuncSetAttribute(warp3d_kernel,
                         cudaFuncAttributeMaxDynamicSharedMemorySize,
                         TILE_FLOATS * sizeof(float));
    (void)attr_set;

    dim3 block(NTHREADS, 1, 1);
    dim3 grid(HH / YT, DD / ZT, BB);               // 24 x 8 x 4 = 768 CTAs
    warp3d_kernel<<<grid, block, TILE_FLOATS * sizeof(float)>>>(img, flow, out);
}

// round 8
// speedup vs baseline: 1.7645x; 1.7645x over previous
#include <cuda_runtime.h>

// Warper3d: 3D trilinear warp (grid_sample, align_corners=False, border pad).
//   img : [B=4, 1, D=64, H=192, W=192] f32
//   flow: [B=4, 3, D=64, H=192, W=192] f32
//   out : [B=4, 1, D=64, H=192, W=192] f32
//
// R7 post-mortem: smem-gather design was occupancy-starved (12 warps/SM,
// occ 18%, all pipes idle). Same design, 960 threads (30 warps/SM) and
// bank-decorrelating tile pitch (196 floats; 192%32==0 made row jitter
// bank-neutral => stacked conflicts). Gathers via LDS; out-of-halo voxels
// (~2-3%) take an exact global fallback.

#define BB 4
#define DD 64
#define HH 192
#define WW 192
#define SP (DD * HH * WW)

#define YT 8
#define ZT 8
#define HALO 3
#define TILE_Y (YT + 2 * HALO)     // 14
#define TILE_Z (ZT + 2 * HALO)     // 14
#define PITCH  196                 // pad: 196%32=4 => banks shift 4 per row
#define TILE_FLOATS (TILE_Z * TILE_Y * PITCH)   // 38,416 floats = 153,664 B
#define NTHREADS 960               // 5 groups of 192 x-lanes, 30 warps

__global__ __launch_bounds__(NTHREADS)
void warp3d_kernel(const float* __restrict__ img,
                   const float* __restrict__ flow,
                   float* __restrict__ out)
{
    extern __shared__ float tile[];

    const int tid   = threadIdx.x;
    const int ybase = blockIdx.x * YT;
    const int zbase = blockIdx.y * ZT;
    const int b     = blockIdx.z;

    const float* ib = img + (size_t)b * SP;
    const float* fb = flow + (size_t)b * 3 * SP;
    float* ob = out + (size_t)b * SP;

    // ---- stage tile: rows (zbase-3..zbase+10) x (ybase-3..ybase+10), clamped
    {
        const int NROW = TILE_Z * TILE_Y;           // 196
        const int QPR  = WW / 4;                    // 48 float4 per row
        for (int j = tid; j < NROW * QPR; j += NTHREADS) {
            int row = j / QPR;
            int q   = j - row * QPR;
            int ty  = row % TILE_Y;
            int tz  = row / TILE_Y;
            int gy  = min(max(ybase - HALO + ty, 0), HH - 1);
            int gz  = min(max(zbase - HALO + tz, 0), DD - 1);
            float4 v = __ldg((const float4*)(ib + (gz * HH + gy) * WW + 4 * q));
            *(float4*)(tile + row * PITCH + 4 * q) = v;   // row*196 floats: 16B aligned
        }
    }
    __syncthreads();

    const int x   = tid % WW;                       // lane-contiguous x
    const int grp = tid / WW;                       // 0..4

    // Reference composition gx=2v/(S-1)-1; ix=((gx+1)*S-1)/2 == v*S/(S-1)-0.5
    const float KX = (float)WW / (float)(WW - 1);
    const float KY = (float)HH / (float)(HH - 1);
    const float KZ = (float)DD / (float)(DD - 1);

    for (int c = grp; c < YT * ZT; c += 5) {
        int y = ybase + (c & 7);
        int z = zbase + (c >> 3);
        int s = (z * HH + y) * WW + x;

        float fx = __ldcs(fb + s);
        float fy = __ldcs(fb + SP + s);
        float fz = __ldcs(fb + 2 * SP + s);

        float ix = fmaf((float)x + fx, KX, -0.5f);
        float iy = fmaf((float)y + fy, KY, -0.5f);
        float iz = fmaf((float)z + fz, KZ, -0.5f);
        ix = fminf(fmaxf(ix, 0.0f), (float)(WW - 1));
        iy = fminf(fmaxf(iy, 0.0f), (float)(HH - 1));
        iz = fminf(fmaxf(iz, 0.0f), (float)(DD - 1));

        float x0f = floorf(ix); float wx = ix - x0f;
        float y0f = floorf(iy); float wy = iy - y0f;
        float z0f = floorf(iz); float wz = iz - z0f;

        int x0 = (int)x0f; int x1 = min(x0 + 1, WW - 1);
        int y0 = (int)y0f; int y1 = min(y0 + 1, HH - 1);
        int z0 = (int)z0f; int z1 = min(z0 + 1, DD - 1);

        float v000, v001, v010, v011, v100, v101, v110, v111;

        int ty0 = y0 - (ybase - HALO);
        int ty1 = y1 - (ybase - HALO);
        int tz0 = z0 - (zbase - HALO);
        int tz1 = z1 - (zbase - HALO);

        bool in_tile = (ty0 >= 0) & (ty1 < TILE_Y) & (tz0 >= 0) & (tz1 < TILE_Z);

        if (in_tile) {
            const float* t00 = tile + (tz0 * TILE_Y + ty0) * PITCH;
            const float* t01 = tile + (tz0 * TILE_Y + ty1) * PITCH;
            const float* t10 = tile + (tz1 * TILE_Y + ty0) * PITCH;
            const float* t11 = tile + (tz1 * TILE_Y + ty1) * PITCH;
            v000 = t00[x0]; v001 = t00[x1];
            v010 = t01[x0]; v011 = t01[x1];
            v100 = t10[x0]; v101 = t10[x1];
            v110 = t11[x0]; v111 = t11[x1];
        } else {
            // rare (~2-3%): exact global gather
            const float* p00 = ib + (z0 * HH + y0) * WW;
            const float* p01 = ib + (z0 * HH + y1) * WW;
            const float* p10 = ib + (z1 * HH + y0) * WW;
            const float* p11 = ib + (z1 * HH + y1) * WW;
            v000 = __ldg(p00 + x0); v001 = __ldg(p00 + x1);
            v010 = __ldg(p01 + x0); v011 = __ldg(p01 + x1);
            v100 = __ldg(p10 + x0); v101 = __ldg(p10 + x1);
            v110 = __ldg(p11 + x0); v111 = __ldg(p11 + x1);
        }

        float c00 = fmaf(wx, v001 - v000, v000);
        float c01 = fmaf(wx, v011 - v010, v010);
        float c10 = fmaf(wx, v101 - v100, v100);
        float c11 = fmaf(wx, v111 - v110, v110);
        float c0  = fmaf(wy, c01 - c00, c00);
        float c1  = fmaf(wy, c11 - c10, c10);
        float r   = fmaf(wz, c1 - c0, c0);

        __stcs(ob + s, r);
    }
}

extern "C" void kernel_launch(void* const* d_in, const int* in_sizes, int n_in,
                              void* d_out, int out_size)
{
    const float* img  = (const float*)d_in[0];
    const float* flow = (const float*)d_in[1];
    float* out = (float*)d_out;

    // idempotent attribute set; capture-legal (not a stream operation)
    cudaFuncSetAttribute(warp3d_kernel,
                         cudaFuncAttributeMaxDynamicSharedMemorySize,
                         TILE_FLOATS * sizeof(float));

    dim3 block(NTHREADS, 1, 1);
    dim3 grid(HH / YT, DD / ZT, BB);               // 24 x 8 x 4 = 768 CTAs
    warp3d_kernel<<<grid, block, TILE_FLOATS * sizeof(float)>>>(img, flow, out);
}

// round 11
// speedup vs baseline: 2.0146x; 1.1418x over previous
#include <cuda_runtime.h>

// Warper3d: 3D trilinear warp (grid_sample, align_corners=False, border pad).
//   img : [B=4, 1, D=64, H=192, W=192] f32
//   flow: [B=4, 3, D=64, H=192, W=192] f32
//   out : [B=4, 1, D=64, H=192, W=192] f32
//
// Model (R3-R8): L1tex-wavefront bound on scalar 4B gathers (random per-lane
// rows; wider gathers regress; smem tiling loses on occupancy/serialization).
// R6 (2 voxels/thread) = 72.2us at issue=32% -> latency slack remains.
// This version: 4 voxels/thread (x-pair x z-pair), 32 independent gathers +
// 6 float2 flow loads in flight, scalar gathers kept at the sector byte floor.
// (R9/R10 benches were infra failures — resubmitting unchanged.)

#define BB 4
#define DD 64
#define HH 192
#define WW 192
#define SP (DD * HH * WW)
#define HW (HH * WW)

#define BTX 96     // x-pair threads (covers all 192 x)
#define BTY 2      // y per block

__global__ __launch_bounds__(BTX * BTY)
void warp3d_kernel(const float* __restrict__ img,
                   const float* __restrict__ flow,
                   float* __restrict__ out)
{
    const int xp = threadIdx.x * 2;                 // 0..190 even
    const int y  = blockIdx.x * BTY + threadIdx.y;  // grid.x = 96
    const int z0v = blockIdx.y * 2;                 // z pair base; grid.y = 32
    const int b  = blockIdx.z;

    const int s0 = (z0v * HH + y) * WW + xp;        // voxel pair at z0v
    const int s1 = s0 + HW;                          // voxel pair at z0v+1

    const float* fb = flow + (size_t)b * 3 * SP;
    // 6 independent coalesced flow loads issued up-front
    float2 fx0 = __ldg((const float2*)(fb + s0));
    float2 fx1 = __ldg((const float2*)(fb + s1));
    float2 fy0 = __ldg((const float2*)(fb + SP + s0));
    float2 fy1 = __ldg((const float2*)(fb + SP + s1));
    float2 fz0 = __ldg((const float2*)(fb + 2 * SP + s0));
    float2 fz1 = __ldg((const float2*)(fb + 2 * SP + s1));

    // Reference composition gx=2v/(S-1)-1; ix=((gx+1)*S-1)/2 == v*S/(S-1)-0.5
    const float KX = (float)WW / (float)(WW - 1);
    const float KY = (float)HH / (float)(HH - 1);
    const float KZ = (float)DD / (float)(DD - 1);

    const float* ib = img + (size_t)b * SP;

    const float fxa[4] = {fx0.x, fx0.y, fx1.x, fx1.y};
    const float fya[4] = {fy0.x, fy0.y, fy1.x, fy1.y};
    const float fza[4] = {fz0.x, fz0.y, fz1.x, fz1.y};

    // ---- phase 1: coordinates + 32 independent gathers
    float wxa[4], wya[4], wza[4];
    float v[4][8];

    #pragma unroll
    for (int k = 0; k < 4; k++) {
        int xv = xp + (k & 1);
        int zv = z0v + (k >> 1);

        float ix = fmaf((float)xv + fxa[k], KX, -0.5f);
        float iy = fmaf((float)y  + fya[k], KY, -0.5f);
        float iz = fmaf((float)zv + fza[k], KZ, -0.5f);
        ix = fminf(fmaxf(ix, 0.0f), (float)(WW - 1));
        iy = fminf(fmaxf(iy, 0.0f), (float)(HH - 1));
        iz = fminf(fmaxf(iz, 0.0f), (float)(DD - 1));

        float x0f = floorf(ix); wxa[k] = ix - x0f;
        float y0f = floorf(iy); wya[k] = iy - y0f;
        float z0f = floorf(iz); wza[k] = iz - z0f;

        int x0 = (int)x0f; int x1 = min(x0 + 1, WW - 1);
        int y0 = (int)y0f; int y1 = min(y0 + 1, HH - 1);
        int z0 = (int)z0f; int z1 = min(z0 + 1, DD - 1);

        const float* p00 = ib + (z0 * HH + y0) * WW;
        const float* p01 = ib + (z0 * HH + y1) * WW;
        const float* p10 = ib + (z1 * HH + y0) * WW;
        const float* p11 = ib + (z1 * HH + y1) * WW;

        v[k][0] = __ldg(p00 + x0);
        v[k][1] = __ldg(p00 + x1);
        v[k][2] = __ldg(p01 + x0);
        v[k][3] = __ldg(p01 + x1);
        v[k][4] = __ldg(p10 + x0);
        v[k][5] = __ldg(p10 + x1);
        v[k][6] = __ldg(p11 + x0);
        v[k][7] = __ldg(p11 + x1);
    }

    // ---- phase 2: interpolation
    float r[4];
    #pragma unroll
    for (int k = 0; k < 4; k++) {
        float wx = wxa[k], wy = wya[k], wz = wza[k];
        float c00 = fmaf(wx, v[k][1] - v[k][0], v[k][0]);
        float c01 = fmaf(wx, v[k][3] - v[k][2], v[k][2]);
        float c10 = fmaf(wx, v[k][5] - v[k][4], v[k][4]);
        float c11 = fmaf(wx, v[k][7] - v[k][6], v[k][6]);
        float c0  = fmaf(wy, c01 - c00, c00);
        float c1  = fmaf(wy, c11 - c10, c10);
        r[k]      = fmaf(wz, c1 - c0, c0);
    }

    float* ob = out + (size_t)b * SP;
    *(float2*)(ob + s0) = make_float2(r[0], r[1]);
    *(float2*)(ob + s1) = make_float2(r[2], r[3]);
}

extern "C" void kernel_launch(void* const* d_in, const int* in_sizes, int n_in,
                              void* d_out, int out_size)
{
    const float* img  = (const float*)d_in[0];
    const float* flow = (const float*)d_in[1];
    float* out = (float*)d_out;

    dim3 block(BTX, BTY, 1);                 // 192 threads
    dim3 grid(HH / BTY, DD / 2, BB);         // 96 x 32 x 4
    warp3d_kernel<<<grid, block>>>(img, flow, out);
}